// round 14
// baseline (speedup 1.0000x reference)
#include <cuda_runtime.h>
#include <cuda_fp16.h>

#define NPTS 100000
#define PCH  96
#define DIMC 192
#define KTAP 27
#define NTAP 81                 // 3*27
#define ZCOL 648                // 81*8

// ---------------- scratch (static device globals; no allocation) ------------
__device__ __half g_v1h[NPTS * PCH];          // v1 fp16
__device__ __half g_v2h[NPTS * DIMC];         // v2 fp16
__device__ float  g_choice[NPTS * 24];
__device__ __half g_aggh[NPTS * DIMC];        // agg fp16
__device__ __half g_xh[NPTS * PCH];           // x fp16
__device__ __half g_wh1[KTAP * PCH * PCH];    // w_v1 fp16 [k][n][c]
__device__ __half g_qw2h[ZCOL * PCH];         // QW fp16 [t*8+m][c=96]
__device__ __half g_zh[(size_t)NPTS * ZCOL];  // z fp16 [n][t*8+m]
__device__ __half g_w2h[DIMC * PCH];          // w_v2 fp16 [j=192][c=96]
__device__ __half g_owh[PCH * DIMC];          // out_w fp16 [j=96][c=192]

// ---------------- sparse-pattern masks --------------------------------------
__constant__ int c_mask_items[3][4][9] = {
  { {0,1,3,6,7,13,-1,-1,-1}, {1,2,9,14,15,17,-1,-1,-1},
    {0,5,6,7,8,10,-1,-1,-1}, {17,19,20,22,23,-1,-1,-1,-1} },
  { {10,11,12,20,21,22,-1,-1,-1}, {1,2,3,4,5,6,10,21,20},
    {3,4,5,6,7,8,9,10,11},        {17,18,19,20,22,23,24,-1,-1} },
  { {0,5,9,13,19,22,-1,-1,-1}, {1,3,7,8,11,16,20,-1,-1},
    {4,6,11,12,18,24,25,-1,-1}, {5,6,10,14,19,23,-1,-1,-1} },
};
__constant__ int c_mask_len[3][4] = {{6,6,6,5},{6,9,9,7},{6,7,7,6}};

// ---------------- mma + cp.async + ldmatrix helpers --------------------------
__device__ __forceinline__ void mma_f16(float* d, const unsigned* a,
                                        const unsigned* b) {
  asm volatile(
    "mma.sync.aligned.m16n8k16.row.col.f32.f16.f16.f32 "
    "{%0,%1,%2,%3}, {%4,%5,%6,%7}, {%8,%9}, {%0,%1,%2,%3};"
    : "+f"(d[0]), "+f"(d[1]), "+f"(d[2]), "+f"(d[3])
    : "r"(a[0]), "r"(a[1]), "r"(a[2]), "r"(a[3]), "r"(b[0]), "r"(b[1]));
}
__device__ __forceinline__ void ldsm_x4(unsigned* r, unsigned addr) {
  asm volatile("ldmatrix.sync.aligned.m8n8.x4.shared.b16 {%0,%1,%2,%3}, [%4];"
    : "=r"(r[0]), "=r"(r[1]), "=r"(r[2]), "=r"(r[3]) : "r"(addr));
}
__device__ __forceinline__ void frag_offsets(int lane, int wm, int wn, int apad,
                                             unsigned aoff[2], unsigned boff[3]) {
  int g = lane >> 3;
  int ar = (g & 1) * 8 + (lane & 7);
  int ac = (g >> 1) * 8;
  aoff[0] = (unsigned)((wm * 32 + ar) * apad + ac) * 2u;
  aoff[1] = (unsigned)((wm * 32 + 16 + ar) * apad + ac) * 2u;
  int br = (g >> 1) * 8 + (lane & 7);
  int bc = (g & 1) * 8;
  #pragma unroll
  for (int p = 0; p < 3; ++p)
    boff[p] = (unsigned)((wn * 48 + p * 16 + br) * apad + bc) * 2u;
}
__device__ __forceinline__ void cpa16(void* dst, const void* src) {
  unsigned d = (unsigned)__cvta_generic_to_shared(dst);
  asm volatile("cp.async.ca.shared.global [%0], [%1], 16;" :: "r"(d), "l"(src));
}
__device__ __forceinline__ void cpa16z(void* dst, const void* src, int sz) {
  unsigned d = (unsigned)__cvta_generic_to_shared(dst);
  asm volatile("cp.async.ca.shared.global [%0], [%1], 16, %2;"
               :: "r"(d), "l"(src), "r"(sz));
}
#define CPA_COMMIT() asm volatile("cp.async.commit_group;" ::: "memory")
#define CPA_WAIT2()  asm volatile("cp.async.wait_group 2;" ::: "memory")
#define CPA_WAIT0()  asm volatile("cp.async.wait_group 0;" ::: "memory")

// =============================================================================
// K0: one-shot fp16 conversions
// =============================================================================
__global__ __launch_bounds__(256) void k0_cvt_x(const float* __restrict__ x) {
  int i = blockIdx.x * 256 + threadIdx.x;
  int stride = gridDim.x * 256;
  for (; i < NPTS * PCH; i += stride) g_xh[i] = __float2half(x[i]);
}
__global__ __launch_bounds__(256) void k0_cvt_w1(const float* __restrict__ w) {
  int k = blockIdx.x;
  const float* src = w + k * PCH * PCH;     // [c][n]
  __half* dst = g_wh1 + k * PCH * PCH;      // [n][c]
  for (int i = threadIdx.x; i < PCH * PCH; i += 256) {
    int n = i / PCH, c = i % PCH;
    dst[i] = __float2half(src[c * PCH + n]);
  }
}
__global__ __launch_bounds__(256) void k0_cvt_qw2(const float* __restrict__ qw) {
  int t = blockIdx.x;                        // tap 0..80
  const float* src = qw + t * (PCH * 8);     // [c=96][m=8]
  for (int i = threadIdx.x; i < 8 * PCH; i += 256) {
    int m = i / PCH, c = i % PCH;
    g_qw2h[(t * 8 + m) * PCH + c] = __float2half(src[c * 8 + m]);
  }
}
__global__ __launch_bounds__(256) void k0_cvt_w2(const float* __restrict__ w2) {
  int i = blockIdx.x * 256 + threadIdx.x;    // [c=96][j=192] -> [j][c]
  if (i < PCH * DIMC) {
    int j = i / PCH, c = i % PCH;
    g_w2h[i] = __float2half(w2[c * DIMC + j]);
  }
}
__global__ __launch_bounds__(256) void k0_cvt_ow(const float* __restrict__ ow) {
  int i = blockIdx.x * 256 + threadIdx.x;    // [c=192][j=96] -> [j][c]
  if (i < PCH * DIMC) {
    int j = i / DIMC, c = i % DIMC;
    g_owh[i] = __float2half(ow[c * PCH + j]);
  }
}

#define K1_APAD 104

// =============================================================================
// K1 (fp16 mma + ldmatrix, 3-stage ring, M=256, 512 threads):
// v1h = fp16(relu(BN( sum_k gather @ W[k] )))
// 3 x 73.2KB = 219.6KB smem, 1 CTA x 16 warps; 2 taps of copy in flight.
// =============================================================================
#define K1_AS (256 * K1_APAD)
#define K1_BS (96 * K1_APAD)
#define K1_STG (K1_AS + K1_BS)
#define K1_SMEM (3 * K1_STG * 2)              // 219648 bytes

__device__ __forceinline__ void k1_issue(
    __half* stg, const int* __restrict__ neis, int k, int n0, int tid)
{
  const int arow = tid >> 1, ahalf = tid & 1;   // 512 threads -> 256 rows
  int n = n0 + arow;
  int nr = (n < NPTS) ? __ldg(&neis[(KTAP + k) * NPTS + n]) : NPTS;
  int sz = (nr < NPTS) ? 16 : 0;
  const __half* srcA = g_xh + (size_t)(nr < NPTS ? nr : 0) * PCH + ahalf * 48;
  __half* dstA = stg + arow * K1_APAD + ahalf * 48;
  #pragma unroll
  for (int i = 0; i < 6; ++i) cpa16z(dstA + i * 8, srcA + i * 8, sz);
  const __half* srcB = g_wh1 + k * PCH * PCH;
  __half* Bs = stg + K1_AS;
  #pragma unroll
  for (int j = 0; j < 3; ++j) {
    int idx = tid + j * 512;                    // 1152 chunks (96 x 12)
    if (idx < 1152) {
      int row = idx / 12, q = idx % 12;
      cpa16(Bs + row * K1_APAD + q * 8, srcB + row * PCH + q * 8);
    }
  }
}

__global__ __launch_bounds__(512) void k1_mma(
    const int* __restrict__ neis, const float* __restrict__ bng,
    const float* __restrict__ bnb)
{
  extern __shared__ char smem8[];
  __half* sm = (__half*)smem8;
  const int tid  = threadIdx.x;
  const int lane = tid & 31;
  const int wid  = tid >> 5;
  const int wm   = wid & 7;                     // 8 M-warps
  const int wn   = wid >> 3;                    // 2 N-warps
  const int n0   = blockIdx.x * 256;

  unsigned aoff[2], boff[3];
  frag_offsets(lane, wm, wn, K1_APAD, aoff, boff);
  const unsigned sm32 = (unsigned)__cvta_generic_to_shared(sm);

  float d[2][6][4] = {};

  #pragma unroll
  for (int p = 0; p < 2; ++p) {
    k1_issue(sm + p * K1_STG, neis, p, n0, tid);
    CPA_COMMIT();
  }

  for (int k = 0; k < KTAP; ++k) {
    if (k + 2 < KTAP)
      k1_issue(sm + ((k + 2) % 3) * K1_STG, neis, k + 2, n0, tid);
    CPA_COMMIT();
    CPA_WAIT2();
    __syncthreads();
    const unsigned As32 = sm32 + (unsigned)((k % 3) * K1_STG) * 2u;
    const unsigned Bs32 = As32 + (unsigned)K1_AS * 2u;
    #pragma unroll
    for (int ks = 0; ks < 6; ++ks) {
      unsigned a[2][4], bf[3][4];
      ldsm_x4(a[0], As32 + aoff[0] + ks * 32);
      ldsm_x4(a[1], As32 + aoff[1] + ks * 32);
      ldsm_x4(bf[0], Bs32 + boff[0] + ks * 32);
      ldsm_x4(bf[1], Bs32 + boff[1] + ks * 32);
      ldsm_x4(bf[2], Bs32 + boff[2] + ks * 32);
      #pragma unroll
      for (int mi = 0; mi < 2; ++mi)
        #pragma unroll
        for (int p = 0; p < 3; ++p) {
          mma_f16(d[mi][2 * p],     a[mi], &bf[p][0]);
          mma_f16(d[mi][2 * p + 1], a[mi], &bf[p][2]);
        }
    }
    __syncthreads();
  }

  #pragma unroll
  for (int mi = 0; mi < 2; ++mi) {
    int r0 = n0 + wm * 32 + mi * 16 + (lane >> 2);
    #pragma unroll
    for (int ni = 0; ni < 6; ++ni) {
      int c = wn * 48 + ni * 8 + (lane & 3) * 2;
      float g0 = __ldg(&bng[c]),     b0 = __ldg(&bnb[c]);
      float g1 = __ldg(&bng[c + 1]), b1 = __ldg(&bnb[c + 1]);
      if (r0 < NPTS) {
        float v0 = fmaxf(fmaf(d[mi][ni][0], g0, b0), 0.f);
        float v1 = fmaxf(fmaf(d[mi][ni][1], g1, b1), 0.f);
        *(__half2*)&g_v1h[(size_t)r0 * PCH + c] = __floats2half2_rn(v0, v1);
      }
      if (r0 + 8 < NPTS) {
        float v0 = fmaxf(fmaf(d[mi][ni][2], g0, b0), 0.f);
        float v1 = fmaxf(fmaf(d[mi][ni][3], g1, b1), 0.f);
        *(__half2*)&g_v1h[(size_t)(r0 + 8) * PCH + c] = __floats2half2_rn(v0, v1);
      }
    }
  }
}

// =============================================================================
// K3a (fp16 mma + ldmatrix): z = xh @ QW  [100k,96]@[96,648]; grid.y=7
// =============================================================================
#define K3A_AS (128 * K1_APAD)
#define K3A_SMEM ((128 + 96) * K1_APAD * 2)

__global__ __launch_bounds__(256) void k3a_z()
{
  extern __shared__ char smem8[];
  __half* As = (__half*)smem8;               // [128][104]
  __half* Bs = As + 128 * K1_APAD;           // [96][104]
  const int tid  = threadIdx.x;
  const int lane = tid & 31;
  const int wid  = tid >> 5;
  const int wm   = wid & 3;
  const int wn   = wid >> 2;
  const int n0   = blockIdx.x * 128;
  const int j0   = blockIdx.y * 96;

  #pragma unroll
  for (int j = 0; j < 6; ++j) {
    int idx = tid + j * 256;                 // 1536 chunks A (128 x 12)
    int row = idx / 12, q = idx % 12;
    int n = n0 + row;
    cpa16z(As + row * K1_APAD + q * 8,
           g_xh + (size_t)(n < NPTS ? n : 0) * PCH + q * 8,
           (n < NPTS) ? 16 : 0);
  }
  #pragma unroll
  for (int j = 0; j < 5; ++j) {
    int idx = tid + j * 256;                 // 1152 chunks B (96 x 12)
    if (idx < 1152) {
      int row = idx / 12, q = idx % 12;
      int jr = j0 + row;
      cpa16z(Bs + row * K1_APAD + q * 8,
             g_qw2h + (size_t)(jr < ZCOL ? jr : 0) * PCH + q * 8,
             (jr < ZCOL) ? 16 : 0);
    }
  }
  CPA_COMMIT(); CPA_WAIT0();
  __syncthreads();

  unsigned aoff[2], boff[3];
  frag_offsets(lane, wm, wn, K1_APAD, aoff, boff);
  const unsigned As32 = (unsigned)__cvta_generic_to_shared(As);
  const unsigned Bs32 = As32 + (unsigned)K3A_AS * 2u;

  float d[2][6][4] = {};
  #pragma unroll
  for (int ks = 0; ks < 6; ++ks) {
    unsigned a[2][4], bf[3][4];
    ldsm_x4(a[0], As32 + aoff[0] + ks * 32);
    ldsm_x4(a[1], As32 + aoff[1] + ks * 32);
    ldsm_x4(bf[0], Bs32 + boff[0] + ks * 32);
    ldsm_x4(bf[1], Bs32 + boff[1] + ks * 32);
    ldsm_x4(bf[2], Bs32 + boff[2] + ks * 32);
    #pragma unroll
    for (int mi = 0; mi < 2; ++mi)
      #pragma unroll
      for (int p = 0; p < 3; ++p) {
        mma_f16(d[mi][2 * p],     a[mi], &bf[p][0]);
        mma_f16(d[mi][2 * p + 1], a[mi], &bf[p][2]);
      }
  }

  #pragma unroll
  for (int mi = 0; mi < 2; ++mi) {
    int r0 = n0 + wm * 32 + mi * 16 + (lane >> 2);
    #pragma unroll
    for (int ni = 0; ni < 6; ++ni) {
      int j = j0 + wn * 48 + ni * 8 + (lane & 3) * 2;
      if (j < ZCOL) {
        if (r0 < NPTS)
          *(__half2*)&g_zh[(size_t)r0 * ZCOL + j] =
              __floats2half2_rn(d[mi][ni][0], d[mi][ni][1]);
        if (r0 + 8 < NPTS)
          *(__half2*)&g_zh[(size_t)(r0 + 8) * ZCOL + j] =
              __floats2half2_rn(d[mi][ni][2], d[mi][ni][3]);
      }
    }
  }
}

// =============================================================================
// K3b: thread-per-point gather of z (16B per tap) + double-softmax epilogue.
// =============================================================================
__global__ __launch_bounds__(256) void k3b_choice(const int* __restrict__ neis)
{
  int n = blockIdx.x * 256 + threadIdx.x;
  if (n >= NPTS) return;

  float qs[3][8];
  unsigned pbv[3];

  #pragma unroll
  for (int d = 0; d < 3; ++d) {
    const int* nd = neis + d * KTAP * NPTS + n;
    int rr[KTAP];
    #pragma unroll
    for (int k = 0; k < KTAP; ++k) rr[k] = __ldg(&nd[k * NPTS]);
    unsigned pb = 0;
    float a[8] = {0.f,0.f,0.f,0.f,0.f,0.f,0.f,0.f};
    #pragma unroll 9
    for (int k = 0; k < KTAP; ++k) {
      int r = rr[k];
      if (r < NPTS) {
        pb |= 1u << k;
        const uint4 zv = *(const uint4*)
            (g_zh + ((size_t)r * NTAP + d * KTAP + k) * 8);
        float2 f0 = __half22float2(*(const __half2*)&zv.x);
        float2 f1 = __half22float2(*(const __half2*)&zv.y);
        float2 f2 = __half22float2(*(const __half2*)&zv.z);
        float2 f3 = __half22float2(*(const __half2*)&zv.w);
        a[0] += f0.x; a[1] += f0.y; a[2] += f1.x; a[3] += f1.y;
        a[4] += f2.x; a[5] += f2.y; a[6] += f3.x; a[7] += f3.y;
      }
    }
    pbv[d] = pb;
    #pragma unroll
    for (int m = 0; m < 8; ++m) qs[d][m] = a[m];
  }

  float t1[3][8];
  #pragma unroll
  for (int d = 0; d < 3; ++d) {
    float v[8];
    #pragma unroll
    for (int mi = 0; mi < 4; ++mi) {
      unsigned ex = 0;
      #pragma unroll
      for (int tt = 0; tt < 9; ++tt) {
        int it = c_mask_items[d][mi][tt];
        if (it >= 0) ex |= (1u << it);
      }
      float keepinv = 1.f / (float)(27 - c_mask_len[d][mi]);
      float spv = (float)__popc(pbv[d] & ~ex & 0x7FFFFFFu) * keepinv;
      v[mi] = (spv + 1e-3f) * 5.f;
    }
    #pragma unroll
    for (int mi = 4; mi < 8; ++mi) v[mi] = 5e-3f;
    float mx = v[0];
    #pragma unroll
    for (int m = 1; m < 8; ++m) mx = fmaxf(mx, v[m]);
    float s = 0.f;
    #pragma unroll
    for (int m = 0; m < 8; ++m) { v[m] = __expf(v[m] - mx); s += v[m]; }
    float inv = 1.f / s;
    #pragma unroll
    for (int m = 0; m < 8; ++m) t1[d][m] = v[m] * inv;
  }
  #pragma unroll
  for (int m = 0; m < 8; ++m) {
    float a0 = (t1[0][m] + 1e-3f) * 5.f;
    float a1 = (t1[1][m] + 1e-3f) * 5.f;
    float a2 = (t1[2][m] + 1e-3f) * 5.f;
    float mx = fmaxf(a0, fmaxf(a1, a2));
    float e0 = __expf(a0 - mx), e1 = __expf(a1 - mx), e2 = __expf(a2 - mx);
    float inv = 1.f / (e0 + e1 + e2);
    t1[0][m] = e0 * inv; t1[1][m] = e1 * inv; t1[2][m] = e2 * inv;
  }
  #pragma unroll
  for (int d = 0; d < 3; ++d) {
    float sv[8];
    float mx = -1e30f;
    #pragma unroll
    for (int m = 0; m < 8; ++m) {
      sv[m] = qs[d][m] * 0.70710678118654752f;
      mx = fmaxf(mx, sv[m]);
    }
    float s = 0.f;
    #pragma unroll
    for (int m = 0; m < 8; ++m) { sv[m] = __expf(sv[m] - mx); s += sv[m]; }
    float inv = 1.f / s;
    #pragma unroll
    for (int m = 0; m < 8; ++m)
      g_choice[n * 24 + d * 8 + m] = sv[m] * inv * t1[d][m];
  }
}

// =============================================================================
// K2 (fp16 mma + ldmatrix): v2h = fp16(relu(BN( v1h @ w_v2 )))
// =============================================================================
#define K2_SMEM ((128 + 96) * K1_APAD * 2)

__global__ __launch_bounds__(256) void k2_mma(
    const float* __restrict__ bng, const float* __restrict__ bnb)
{
  extern __shared__ char smem8[];
  __half* As = (__half*)smem8;
  __half* Bs = As + 128 * K1_APAD;
  const int tid  = threadIdx.x;
  const int lane = tid & 31;
  const int wid  = tid >> 5;
  const int wm   = wid & 3;
  const int wn   = wid >> 2;
  const int n0   = blockIdx.x * 128;
  const int j0   = blockIdx.y * 96;

  #pragma unroll
  for (int j = 0; j < 6; ++j) {
    int idx = tid + j * 256;
    int row = idx / 12, q = idx % 12;
    int n = n0 + row;
    cpa16z(As + row * K1_APAD + q * 8,
           g_v1h + (size_t)(n < NPTS ? n : 0) * PCH + q * 8,
           (n < NPTS) ? 16 : 0);
  }
  #pragma unroll
  for (int j = 0; j < 5; ++j) {
    int idx = tid + j * 256;
    if (idx < 1152) {
      int row = idx / 12, q = idx % 12;
      cpa16(Bs + row * K1_APAD + q * 8, g_w2h + (j0 + row) * PCH + q * 8);
    }
  }
  CPA_COMMIT(); CPA_WAIT0();
  __syncthreads();

  unsigned aoff[2], boff[3];
  frag_offsets(lane, wm, wn, K1_APAD, aoff, boff);
  const unsigned As32 = (unsigned)__cvta_generic_to_shared(As);
  const unsigned Bs32 = As32 + (unsigned)K3A_AS * 2u;

  float d[2][6][4] = {};
  #pragma unroll
  for (int ks = 0; ks < 6; ++ks) {
    unsigned a[2][4], bf[3][4];
    ldsm_x4(a[0], As32 + aoff[0] + ks * 32);
    ldsm_x4(a[1], As32 + aoff[1] + ks * 32);
    ldsm_x4(bf[0], Bs32 + boff[0] + ks * 32);
    ldsm_x4(bf[1], Bs32 + boff[1] + ks * 32);
    ldsm_x4(bf[2], Bs32 + boff[2] + ks * 32);
    #pragma unroll
    for (int mi = 0; mi < 2; ++mi)
      #pragma unroll
      for (int p = 0; p < 3; ++p) {
        mma_f16(d[mi][2 * p],     a[mi], &bf[p][0]);
        mma_f16(d[mi][2 * p + 1], a[mi], &bf[p][2]);
      }
  }

  #pragma unroll
  for (int mi = 0; mi < 2; ++mi) {
    int r0 = n0 + wm * 32 + mi * 16 + (lane >> 2);
    #pragma unroll
    for (int ni = 0; ni < 6; ++ni) {
      int j = j0 + wn * 48 + ni * 8 + (lane & 3) * 2;
      float g0 = __ldg(&bng[j]),     b0 = __ldg(&bnb[j]);
      float g1 = __ldg(&bng[j + 1]), b1 = __ldg(&bnb[j + 1]);
      if (r0 < NPTS) {
        float v0 = fmaxf(fmaf(d[mi][ni][0], g0, b0), 0.f);
        float v1 = fmaxf(fmaf(d[mi][ni][1], g1, b1), 0.f);
        *(__half2*)&g_v2h[(size_t)r0 * DIMC + j] = __floats2half2_rn(v0, v1);
      }
      if (r0 + 8 < NPTS) {
        float v0 = fmaxf(fmaf(d[mi][ni][2], g0, b0), 0.f);
        float v1 = fmaxf(fmaf(d[mi][ni][3], g1, b1), 0.f);
        *(__half2*)&g_v2h[(size_t)(r0 + 8) * DIMC + j] = __floats2half2_rn(v0, v1);
      }
    }
  }
}

// =============================================================================
// K4: aggh = fp16(sum_d choice * sum_k cb*gather(v2h)); cb staged as fp16
// =============================================================================
#define K4_SMEM (15552 * 2)       // 31104 bytes

__global__ __launch_bounds__(256) void k4_agg(
    const int* __restrict__ neis, const float* __restrict__ cb)
{
  extern __shared__ char smem8[];
  __half2* ks = (__half2*)smem8;   // 7776 half2
  for (int i = threadIdx.x; i < 7776; i += 256) {
    float2 f = ((const float2*)cb)[i];
    ks[i] = __floats2half2_rn(f.x, f.y);
  }
  __syncthreads();

  const int lane = threadIdx.x & 31;
  const int w    = threadIdx.x >> 5;
  const int n0   = blockIdx.x * 128 + w * 16;

  for (int pi = 0; pi < 16; ++pi) {
    int n = n0 + pi;
    if (n >= NPTS) break;
    float agg[6] = {0.f,0.f,0.f,0.f,0.f,0.f};
    #pragma unroll
    for (int d = 0; d < 3; ++d) {
      const int* nd = neis + d*KTAP*NPTS + n;
      int rr[KTAP];
      #pragma unroll
      for (int k = 0; k < KTAP; ++k) rr[k] = __ldg(&nd[k*NPTS]);
      float pd[6] = {0.f,0.f,0.f,0.f,0.f,0.f};
      #pragma unroll 9
      for (int k = 0; k < KTAP; ++k) {
        int r = rr[k];
        if (r < NPTS) {
          const __half2* vr = (const __half2*)(g_v2h + (size_t)r * DIMC);
          const __half2* kk = ks + (d*KTAP + k)*96;
          #pragma unroll
          for (int i = 0; i < 3; ++i) {
            float2 f = __half22float2(vr[lane + 32*i]);
            float2 kf = __half22float2(kk[lane + 32*i]);
            pd[2*i]   = fmaf(kf.x, f.x, pd[2*i]);
            pd[2*i+1] = fmaf(kf.y, f.y, pd[2*i+1]);
          }
        }
      }
      #pragma unroll
      for (int i = 0; i < 3; ++i) {
        int c = lane*2 + 64*i;
        float ch = g_choice[n*24 + d*8 + (c/24)];
        agg[2*i]   += pd[2*i]   * ch;
        agg[2*i+1] += pd[2*i+1] * ch;
      }
    }
    #pragma unroll
    for (int i = 0; i < 3; ++i) {
      int c = lane*2 + 64*i;
      *(__half2*)&g_aggh[(size_t)n*DIMC + c] =
          __floats2half2_rn(agg[2*i], agg[2*i+1]);
    }
  }
}

// =============================================================================
// K5 (fp16 mma + ldmatrix): out = relu(BN( aggh @ out_w )) + x
// =============================================================================
#define K5_APAD 200
#define K5_SMEM ((128 + 96) * K5_APAD * 2)

__global__ __launch_bounds__(256) void k5_mma(
    const float* __restrict__ x, const float* __restrict__ bng,
    const float* __restrict__ bnb, float* __restrict__ out)
{
  extern __shared__ char smem8[];
  __half* As = (__half*)smem8;
  __half* Bs = As + 128 * K5_APAD;
  const int tid  = threadIdx.x;
  const int lane = tid & 31;
  const int wid  = tid >> 5;
  const int wm   = wid & 3;
  const int wn   = wid >> 2;
  const int n0   = blockIdx.x * 128;

  #pragma unroll
  for (int j = 0; j < 12; ++j) {
    int idx = tid + j * 256;
    int row = idx / 24, q = idx % 24;
    int n = n0 + row;
    cpa16z(As + row * K5_APAD + q * 8,
           g_aggh + (size_t)(n < NPTS ? n : 0) * DIMC + q * 8,
           (n < NPTS) ? 16 : 0);
  }
  #pragma unroll
  for (int j = 0; j < 9; ++j) {
    int idx = tid + j * 256;
    int row = idx / 24, q = idx % 24;
    cpa16(Bs + row * K5_APAD + q * 8, g_owh + row * DIMC + q * 8);
  }
  CPA_COMMIT(); CPA_WAIT0();
  __syncthreads();

  unsigned aoff[2], boff[3];
  frag_offsets(lane, wm, wn, K5_APAD, aoff, boff);
  const unsigned As32 = (unsigned)__cvta_generic_to_shared(As);
  const unsigned Bs32 = As32 + (unsigned)(128 * K5_APAD) * 2u;

  float d[2][6][4] = {};
  #pragma unroll
  for (int ks = 0; ks < 12; ++ks) {
    unsigned a[2][4], bf[3][4];
    ldsm_x4(a[0], As32 + aoff[0] + ks * 32);
    ldsm_x4(a[1], As32 + aoff[1] + ks * 32);
    ldsm_x4(bf[0], Bs32 + boff[0] + ks * 32);
    ldsm_x4(bf[1], Bs32 + boff[1] + ks * 32);
    ldsm_x4(bf[2], Bs32 + boff[2] + ks * 32);
    #pragma unroll
    for (int mi = 0; mi < 2; ++mi)
      #pragma unroll
      for (int p = 0; p < 3; ++p) {
        mma_f16(d[mi][2 * p],     a[mi], &bf[p][0]);
        mma_f16(d[mi][2 * p + 1], a[mi], &bf[p][2]);
      }
  }

  #pragma unroll
  for (int mi = 0; mi < 2; ++mi) {
    int r0 = n0 + wm * 32 + mi * 16 + (lane >> 2);
    #pragma unroll
    for (int ni = 0; ni < 6; ++ni) {
      int c = wn * 48 + ni * 8 + (lane & 3) * 2;
      float g0 = __ldg(&bng[c]),     b0 = __ldg(&bnb[c]);
      float g1 = __ldg(&bng[c + 1]), b1 = __ldg(&bnb[c + 1]);
      if (r0 < NPTS) {
        float2 v;
        v.x = fmaxf(fmaf(d[mi][ni][0], g0, b0), 0.f) + x[(size_t)r0 * PCH + c];
        v.y = fmaxf(fmaf(d[mi][ni][1], g1, b1), 0.f) + x[(size_t)r0 * PCH + c + 1];
        *(float2*)&out[(size_t)r0 * PCH + c] = v;
      }
      if (r0 + 8 < NPTS) {
        float2 v;
        v.x = fmaxf(fmaf(d[mi][ni][2], g0, b0), 0.f) + x[(size_t)(r0+8) * PCH + c];
        v.y = fmaxf(fmaf(d[mi][ni][3], g1, b1), 0.f) + x[(size_t)(r0+8) * PCH + c + 1];
        *(float2*)&out[(size_t)(r0 + 8) * PCH + c] = v;
      }
    }
  }
}

// =============================================================================
extern "C" void kernel_launch(void* const* d_in, const int* in_sizes, int n_in,
                              void* d_out, int out_size)
{
  const float* x    = (const float*)d_in[0];
  const int*   neis = (const int*)  d_in[1];
  const float* w_v1 = (const float*)d_in[2];
  const float* bn1g = (const float*)d_in[3];
  const float* bn1b = (const float*)d_in[4];
  const float* w_v2 = (const float*)d_in[5];
  const float* bn2g = (const float*)d_in[6];
  const float* bn2b = (const float*)d_in[7];
  const float* q_w  = (const float*)d_in[8];
  const float* cbk  = (const float*)d_in[9];
  const float* outw = (const float*)d_in[10];
  const float* obng = (const float*)d_in[11];
  const float* obnb = (const float*)d_in[12];
  float* out = (float*)d_out;

  cudaFuncSetAttribute(k3a_z,   cudaFuncAttributeMaxDynamicSharedMemorySize, K3A_SMEM);
  cudaFuncSetAttribute(k1_mma,  cudaFuncAttributeMaxDynamicSharedMemorySize, K1_SMEM);
  cudaFuncSetAttribute(k2_mma,  cudaFuncAttributeMaxDynamicSharedMemorySize, K2_SMEM);
  cudaFuncSetAttribute(k4_agg,  cudaFuncAttributeMaxDynamicSharedMemorySize, K4_SMEM);
  cudaFuncSetAttribute(k5_mma,  cudaFuncAttributeMaxDynamicSharedMemorySize, K5_SMEM);

  // launch index 3 (0-based) is what ncu captures -> k1 there
  k0_cvt_x   <<<512, 256>>>(x);                                  // 0
  k0_cvt_w1  <<<KTAP, 256>>>(w_v1);                              // 1
  k0_cvt_qw2 <<<NTAP, 256>>>(q_w);                               // 2
  k1_mma     <<<(NPTS + 255) / 256, 512, K1_SMEM>>>(neis, bn1g, bn1b); // 3 <- prof
  k0_cvt_w2  <<<(PCH * DIMC + 255) / 256, 256>>>(w_v2);          // 4
  k0_cvt_ow  <<<(PCH * DIMC + 255) / 256, 256>>>(outw);          // 5
  k3a_z      <<<dim3((NPTS + 127) / 128, 7), 256, K3A_SMEM>>>(); // 6
  k3b_choice <<<(NPTS + 255) / 256, 256>>>(neis);                // 7
  k2_mma     <<<dim3((NPTS + 127) / 128, 2), 256, K2_SMEM>>>(bn2g, bn2b);
  k4_agg     <<<(NPTS + 127) / 128, 256, K4_SMEM>>>(neis, cbk);
  k5_mma     <<<(NPTS + 127) / 128, 256, K5_SMEM>>>(x, obng, obnb, out);
}

// round 15
// speedup vs baseline: 1.0785x; 1.0785x over previous
#include <cuda_runtime.h>
#include <cuda_fp16.h>

#define NPTS 100000
#define PCH  96
#define DIMC 192
#define KTAP 27
#define NTAP 81                 // 3*27
#define ZCOL 648                // 81*8

// ---------------- scratch (static device globals; no allocation) ------------
__device__ __half g_v1h[NPTS * PCH];          // v1 fp16
__device__ __half g_v2h[NPTS * DIMC];         // v2 fp16
__device__ float  g_choice[NPTS * 24];
__device__ __half g_aggh[NPTS * DIMC];        // agg fp16
__device__ __half g_xh[NPTS * PCH];           // x fp16
__device__ __half g_wh1[KTAP * PCH * PCH];    // w_v1 fp16 [k][n][c]
__device__ __half g_qw2h[ZCOL * PCH];         // QW fp16 [t*8+m][c=96]
__device__ __half g_zh[(size_t)NPTS * ZCOL];  // z fp16 [n][t*8+m]
__device__ __half g_w2h[DIMC * PCH];          // w_v2 fp16 [j=192][c=96]
__device__ __half g_owh[PCH * DIMC];          // out_w fp16 [j=96][c=192]

// ---------------- sparse-pattern masks --------------------------------------
__constant__ int c_mask_items[3][4][9] = {
  { {0,1,3,6,7,13,-1,-1,-1}, {1,2,9,14,15,17,-1,-1,-1},
    {0,5,6,7,8,10,-1,-1,-1}, {17,19,20,22,23,-1,-1,-1,-1} },
  { {10,11,12,20,21,22,-1,-1,-1}, {1,2,3,4,5,6,10,21,20},
    {3,4,5,6,7,8,9,10,11},        {17,18,19,20,22,23,24,-1,-1} },
  { {0,5,9,13,19,22,-1,-1,-1}, {1,3,7,8,11,16,20,-1,-1},
    {4,6,11,12,18,24,25,-1,-1}, {5,6,10,14,19,23,-1,-1,-1} },
};
__constant__ int c_mask_len[3][4] = {{6,6,6,5},{6,9,9,7},{6,7,7,6}};

// ---------------- mma + cp.async + ldmatrix helpers --------------------------
__device__ __forceinline__ void mma_f16(float* d, const unsigned* a,
                                        const unsigned* b) {
  asm volatile(
    "mma.sync.aligned.m16n8k16.row.col.f32.f16.f16.f32 "
    "{%0,%1,%2,%3}, {%4,%5,%6,%7}, {%8,%9}, {%0,%1,%2,%3};"
    : "+f"(d[0]), "+f"(d[1]), "+f"(d[2]), "+f"(d[3])
    : "r"(a[0]), "r"(a[1]), "r"(a[2]), "r"(a[3]), "r"(b[0]), "r"(b[1]));
}
__device__ __forceinline__ void ldsm_x4(unsigned* r, unsigned addr) {
  asm volatile("ldmatrix.sync.aligned.m8n8.x4.shared.b16 {%0,%1,%2,%3}, [%4];"
    : "=r"(r[0]), "=r"(r[1]), "=r"(r[2]), "=r"(r[3]) : "r"(addr));
}
__device__ __forceinline__ void frag_offsets(int lane, int wm, int wn, int apad,
                                             unsigned aoff[2], unsigned boff[3]) {
  int g = lane >> 3;
  int ar = (g & 1) * 8 + (lane & 7);
  int ac = (g >> 1) * 8;
  aoff[0] = (unsigned)((wm * 32 + ar) * apad + ac) * 2u;
  aoff[1] = (unsigned)((wm * 32 + 16 + ar) * apad + ac) * 2u;
  int br = (g >> 1) * 8 + (lane & 7);
  int bc = (g & 1) * 8;
  #pragma unroll
  for (int p = 0; p < 3; ++p)
    boff[p] = (unsigned)((wn * 48 + p * 16 + br) * apad + bc) * 2u;
}
__device__ __forceinline__ void cpa16(void* dst, const void* src) {
  unsigned d = (unsigned)__cvta_generic_to_shared(dst);
  asm volatile("cp.async.ca.shared.global [%0], [%1], 16;" :: "r"(d), "l"(src));
}
__device__ __forceinline__ void cpa16z(void* dst, const void* src, int sz) {
  unsigned d = (unsigned)__cvta_generic_to_shared(dst);
  asm volatile("cp.async.ca.shared.global [%0], [%1], 16, %2;"
               :: "r"(d), "l"(src), "r"(sz));
}
#define CPA_COMMIT() asm volatile("cp.async.commit_group;" ::: "memory")
#define CPA_WAIT1()  asm volatile("cp.async.wait_group 1;" ::: "memory")
#define CPA_WAIT0()  asm volatile("cp.async.wait_group 0;" ::: "memory")

// =============================================================================
// K0: one-shot fp16 conversions
// =============================================================================
__global__ __launch_bounds__(256) void k0_cvt_x(const float* __restrict__ x) {
  int i = blockIdx.x * 256 + threadIdx.x;
  int stride = gridDim.x * 256;
  for (; i < NPTS * PCH; i += stride) g_xh[i] = __float2half(x[i]);
}
__global__ __launch_bounds__(256) void k0_cvt_w1(const float* __restrict__ w) {
  int k = blockIdx.x;
  const float* src = w + k * PCH * PCH;     // [c][n]
  __half* dst = g_wh1 + k * PCH * PCH;      // [n][c]
  for (int i = threadIdx.x; i < PCH * PCH; i += 256) {
    int n = i / PCH, c = i % PCH;
    dst[i] = __float2half(src[c * PCH + n]);
  }
}
__global__ __launch_bounds__(256) void k0_cvt_qw2(const float* __restrict__ qw) {
  int t = blockIdx.x;                        // tap 0..80
  const float* src = qw + t * (PCH * 8);     // [c=96][m=8]
  for (int i = threadIdx.x; i < 8 * PCH; i += 256) {
    int m = i / PCH, c = i % PCH;
    g_qw2h[(t * 8 + m) * PCH + c] = __float2half(src[c * 8 + m]);
  }
}
__global__ __launch_bounds__(256) void k0_cvt_w2(const float* __restrict__ w2) {
  int i = blockIdx.x * 256 + threadIdx.x;    // [c=96][j=192] -> [j][c]
  if (i < PCH * DIMC) {
    int j = i / PCH, c = i % PCH;
    g_w2h[i] = __float2half(w2[c * DIMC + j]);
  }
}
__global__ __launch_bounds__(256) void k0_cvt_ow(const float* __restrict__ ow) {
  int i = blockIdx.x * 256 + threadIdx.x;    // [c=192][j=96] -> [j][c]
  if (i < PCH * DIMC) {
    int j = i / DIMC, c = i % DIMC;
    g_owh[i] = __float2half(ow[c * PCH + j]);
  }
}

#define K1_APAD 104

// =============================================================================
// K1 (fp16 mma + ldmatrix, 2-stage, M=128): best-measured k1 variant (round 12)
// =============================================================================
#define K1_AS (128 * K1_APAD)
#define K1_BS (96 * K1_APAD)
#define K1_STG (K1_AS + K1_BS)
#define K1_SMEM (2 * K1_STG * 2)              // 93184 bytes

__device__ __forceinline__ void k1_issue(
    __half* stg, const int* __restrict__ neis, int k, int n0, int tid)
{
  const int arow = tid >> 1, ahalf = tid & 1;
  int n = n0 + arow;
  int nr = (n < NPTS) ? __ldg(&neis[(KTAP + k) * NPTS + n]) : NPTS;
  int sz = (nr < NPTS) ? 16 : 0;
  const __half* srcA = g_xh + (size_t)(nr < NPTS ? nr : 0) * PCH + ahalf * 48;
  __half* dstA = stg + arow * K1_APAD + ahalf * 48;
  #pragma unroll
  for (int i = 0; i < 6; ++i) cpa16z(dstA + i * 8, srcA + i * 8, sz);
  const __half* srcB = g_wh1 + k * PCH * PCH;
  __half* Bs = stg + K1_AS;
  #pragma unroll
  for (int j = 0; j < 5; ++j) {
    int idx = tid + j * 256;
    if (idx < 1152) {
      int row = idx / 12, q = idx % 12;
      cpa16(Bs + row * K1_APAD + q * 8, srcB + row * PCH + q * 8);
    }
  }
}

__global__ __launch_bounds__(256) void k1_mma(
    const int* __restrict__ neis, const float* __restrict__ bng,
    const float* __restrict__ bnb)
{
  extern __shared__ char smem8[];
  __half* sm = (__half*)smem8;
  const int tid  = threadIdx.x;
  const int lane = tid & 31;
  const int wid  = tid >> 5;
  const int wm   = wid & 3;
  const int wn   = wid >> 2;
  const int n0   = blockIdx.x * 128;

  unsigned aoff[2], boff[3];
  frag_offsets(lane, wm, wn, K1_APAD, aoff, boff);
  const unsigned sm32 = (unsigned)__cvta_generic_to_shared(sm);

  float d[2][6][4] = {};

  k1_issue(sm, neis, 0, n0, tid);
  CPA_COMMIT();

  for (int k = 0; k < KTAP; ++k) {
    if (k + 1 < KTAP) {
      k1_issue(sm + ((k + 1) & 1) * K1_STG, neis, k + 1, n0, tid);
      CPA_COMMIT();
      CPA_WAIT1();
    } else {
      CPA_WAIT0();
    }
    __syncthreads();
    const unsigned As32 = sm32 + (unsigned)((k & 1) * K1_STG) * 2u;
    const unsigned Bs32 = As32 + (unsigned)K1_AS * 2u;
    #pragma unroll
    for (int ks = 0; ks < 6; ++ks) {
      unsigned a[2][4], bf[3][4];
      ldsm_x4(a[0], As32 + aoff[0] + ks * 32);
      ldsm_x4(a[1], As32 + aoff[1] + ks * 32);
      ldsm_x4(bf[0], Bs32 + boff[0] + ks * 32);
      ldsm_x4(bf[1], Bs32 + boff[1] + ks * 32);
      ldsm_x4(bf[2], Bs32 + boff[2] + ks * 32);
      #pragma unroll
      for (int mi = 0; mi < 2; ++mi)
        #pragma unroll
        for (int p = 0; p < 3; ++p) {
          mma_f16(d[mi][2 * p],     a[mi], &bf[p][0]);
          mma_f16(d[mi][2 * p + 1], a[mi], &bf[p][2]);
        }
    }
    __syncthreads();
  }

  #pragma unroll
  for (int mi = 0; mi < 2; ++mi) {
    int r0 = n0 + wm * 32 + mi * 16 + (lane >> 2);
    #pragma unroll
    for (int ni = 0; ni < 6; ++ni) {
      int c = wn * 48 + ni * 8 + (lane & 3) * 2;
      float g0 = __ldg(&bng[c]),     b0 = __ldg(&bnb[c]);
      float g1 = __ldg(&bng[c + 1]), b1 = __ldg(&bnb[c + 1]);
      if (r0 < NPTS) {
        float v0 = fmaxf(fmaf(d[mi][ni][0], g0, b0), 0.f);
        float v1 = fmaxf(fmaf(d[mi][ni][1], g1, b1), 0.f);
        *(__half2*)&g_v1h[(size_t)r0 * PCH + c] = __floats2half2_rn(v0, v1);
      }
      if (r0 + 8 < NPTS) {
        float v0 = fmaxf(fmaf(d[mi][ni][2], g0, b0), 0.f);
        float v1 = fmaxf(fmaf(d[mi][ni][3], g1, b1), 0.f);
        *(__half2*)&g_v1h[(size_t)(r0 + 8) * PCH + c] = __floats2half2_rn(v0, v1);
      }
    }
  }
}

// =============================================================================
// K3a (fp16 mma + ldmatrix): z = xh @ QW  [100k,96]@[96,648]; grid.y=7
// =============================================================================
#define K3A_AS (128 * K1_APAD)
#define K3A_SMEM ((128 + 96) * K1_APAD * 2)

__global__ __launch_bounds__(256) void k3a_z()
{
  extern __shared__ char smem8[];
  __half* As = (__half*)smem8;               // [128][104]
  __half* Bs = As + 128 * K1_APAD;           // [96][104]
  const int tid  = threadIdx.x;
  const int lane = tid & 31;
  const int wid  = tid >> 5;
  const int wm   = wid & 3;
  const int wn   = wid >> 2;
  const int n0   = blockIdx.x * 128;
  const int j0   = blockIdx.y * 96;

  #pragma unroll
  for (int j = 0; j < 6; ++j) {
    int idx = tid + j * 256;                 // 1536 chunks A (128 x 12)
    int row = idx / 12, q = idx % 12;
    int n = n0 + row;
    cpa16z(As + row * K1_APAD + q * 8,
           g_xh + (size_t)(n < NPTS ? n : 0) * PCH + q * 8,
           (n < NPTS) ? 16 : 0);
  }
  #pragma unroll
  for (int j = 0; j < 5; ++j) {
    int idx = tid + j * 256;                 // 1152 chunks B (96 x 12)
    if (idx < 1152) {
      int row = idx / 12, q = idx % 12;
      int jr = j0 + row;
      cpa16z(Bs + row * K1_APAD + q * 8,
             g_qw2h + (size_t)(jr < ZCOL ? jr : 0) * PCH + q * 8,
             (jr < ZCOL) ? 16 : 0);
    }
  }
  CPA_COMMIT(); CPA_WAIT0();
  __syncthreads();

  unsigned aoff[2], boff[3];
  frag_offsets(lane, wm, wn, K1_APAD, aoff, boff);
  const unsigned As32 = (unsigned)__cvta_generic_to_shared(As);
  const unsigned Bs32 = As32 + (unsigned)K3A_AS * 2u;

  float d[2][6][4] = {};
  #pragma unroll
  for (int ks = 0; ks < 6; ++ks) {
    unsigned a[2][4], bf[3][4];
    ldsm_x4(a[0], As32 + aoff[0] + ks * 32);
    ldsm_x4(a[1], As32 + aoff[1] + ks * 32);
    ldsm_x4(bf[0], Bs32 + boff[0] + ks * 32);
    ldsm_x4(bf[1], Bs32 + boff[1] + ks * 32);
    ldsm_x4(bf[2], Bs32 + boff[2] + ks * 32);
    #pragma unroll
    for (int mi = 0; mi < 2; ++mi)
      #pragma unroll
      for (int p = 0; p < 3; ++p) {
        mma_f16(d[mi][2 * p],     a[mi], &bf[p][0]);
        mma_f16(d[mi][2 * p + 1], a[mi], &bf[p][2]);
      }
  }

  #pragma unroll
  for (int mi = 0; mi < 2; ++mi) {
    int r0 = n0 + wm * 32 + mi * 16 + (lane >> 2);
    #pragma unroll
    for (int ni = 0; ni < 6; ++ni) {
      int j = j0 + wn * 48 + ni * 8 + (lane & 3) * 2;
      if (j < ZCOL) {
        if (r0 < NPTS)
          *(__half2*)&g_zh[(size_t)r0 * ZCOL + j] =
              __floats2half2_rn(d[mi][ni][0], d[mi][ni][1]);
        if (r0 + 8 < NPTS)
          *(__half2*)&g_zh[(size_t)(r0 + 8) * ZCOL + j] =
              __floats2half2_rn(d[mi][ni][2], d[mi][ni][3]);
      }
    }
  }
}

// =============================================================================
// K3b: thread-per-point gather of z (16B per tap) + double-softmax epilogue.
// =============================================================================
__global__ __launch_bounds__(256) void k3b_choice(const int* __restrict__ neis)
{
  int n = blockIdx.x * 256 + threadIdx.x;
  if (n >= NPTS) return;

  float qs[3][8];
  unsigned pbv[3];

  #pragma unroll
  for (int d = 0; d < 3; ++d) {
    const int* nd = neis + d * KTAP * NPTS + n;
    int rr[KTAP];
    #pragma unroll
    for (int k = 0; k < KTAP; ++k) rr[k] = __ldg(&nd[k * NPTS]);
    unsigned pb = 0;
    float a[8] = {0.f,0.f,0.f,0.f,0.f,0.f,0.f,0.f};
    #pragma unroll 9
    for (int k = 0; k < KTAP; ++k) {
      int r = rr[k];
      if (r < NPTS) {
        pb |= 1u << k;
        const uint4 zv = *(const uint4*)
            (g_zh + ((size_t)r * NTAP + d * KTAP + k) * 8);
        float2 f0 = __half22float2(*(const __half2*)&zv.x);
        float2 f1 = __half22float2(*(const __half2*)&zv.y);
        float2 f2 = __half22float2(*(const __half2*)&zv.z);
        float2 f3 = __half22float2(*(const __half2*)&zv.w);
        a[0] += f0.x; a[1] += f0.y; a[2] += f1.x; a[3] += f1.y;
        a[4] += f2.x; a[5] += f2.y; a[6] += f3.x; a[7] += f3.y;
      }
    }
    pbv[d] = pb;
    #pragma unroll
    for (int m = 0; m < 8; ++m) qs[d][m] = a[m];
  }

  float t1[3][8];
  #pragma unroll
  for (int d = 0; d < 3; ++d) {
    float v[8];
    #pragma unroll
    for (int mi = 0; mi < 4; ++mi) {
      unsigned ex = 0;
      #pragma unroll
      for (int tt = 0; tt < 9; ++tt) {
        int it = c_mask_items[d][mi][tt];
        if (it >= 0) ex |= (1u << it);
      }
      float keepinv = 1.f / (float)(27 - c_mask_len[d][mi]);
      float spv = (float)__popc(pbv[d] & ~ex & 0x7FFFFFFu) * keepinv;
      v[mi] = (spv + 1e-3f) * 5.f;
    }
    #pragma unroll
    for (int mi = 4; mi < 8; ++mi) v[mi] = 5e-3f;
    float mx = v[0];
    #pragma unroll
    for (int m = 1; m < 8; ++m) mx = fmaxf(mx, v[m]);
    float s = 0.f;
    #pragma unroll
    for (int m = 0; m < 8; ++m) { v[m] = __expf(v[m] - mx); s += v[m]; }
    float inv = 1.f / s;
    #pragma unroll
    for (int m = 0; m < 8; ++m) t1[d][m] = v[m] * inv;
  }
  #pragma unroll
  for (int m = 0; m < 8; ++m) {
    float a0 = (t1[0][m] + 1e-3f) * 5.f;
    float a1 = (t1[1][m] + 1e-3f) * 5.f;
    float a2 = (t1[2][m] + 1e-3f) * 5.f;
    float mx = fmaxf(a0, fmaxf(a1, a2));
    float e0 = __expf(a0 - mx), e1 = __expf(a1 - mx), e2 = __expf(a2 - mx);
    float inv = 1.f / (e0 + e1 + e2);
    t1[0][m] = e0 * inv; t1[1][m] = e1 * inv; t1[2][m] = e2 * inv;
  }
  #pragma unroll
  for (int d = 0; d < 3; ++d) {
    float sv[8];
    float mx = -1e30f;
    #pragma unroll
    for (int m = 0; m < 8; ++m) {
      sv[m] = qs[d][m] * 0.70710678118654752f;
      mx = fmaxf(mx, sv[m]);
    }
    float s = 0.f;
    #pragma unroll
    for (int m = 0; m < 8; ++m) { sv[m] = __expf(sv[m] - mx); s += sv[m]; }
    float inv = 1.f / s;
    #pragma unroll
    for (int m = 0; m < 8; ++m)
      g_choice[n * 24 + d * 8 + m] = sv[m] * inv * t1[d][m];
  }
}

// =============================================================================
// K2 (fp16 mma + ldmatrix): v2h = fp16(relu(BN( v1h @ w_v2 )))
// =============================================================================
#define K2_SMEM ((128 + 96) * K1_APAD * 2)

__global__ __launch_bounds__(256) void k2_mma(
    const float* __restrict__ bng, const float* __restrict__ bnb)
{
  extern __shared__ char smem8[];
  __half* As = (__half*)smem8;
  __half* Bs = As + 128 * K1_APAD;
  const int tid  = threadIdx.x;
  const int lane = tid & 31;
  const int wid  = tid >> 5;
  const int wm   = wid & 3;
  const int wn   = wid >> 2;
  const int n0   = blockIdx.x * 128;
  const int j0   = blockIdx.y * 96;

  #pragma unroll
  for (int j = 0; j < 6; ++j) {
    int idx = tid + j * 256;
    int row = idx / 12, q = idx % 12;
    int n = n0 + row;
    cpa16z(As + row * K1_APAD + q * 8,
           g_v1h + (size_t)(n < NPTS ? n : 0) * PCH + q * 8,
           (n < NPTS) ? 16 : 0);
  }
  #pragma unroll
  for (int j = 0; j < 5; ++j) {
    int idx = tid + j * 256;
    if (idx < 1152) {
      int row = idx / 12, q = idx % 12;
      cpa16(Bs + row * K1_APAD + q * 8, g_w2h + (j0 + row) * PCH + q * 8);
    }
  }
  CPA_COMMIT(); CPA_WAIT0();
  __syncthreads();

  unsigned aoff[2], boff[3];
  frag_offsets(lane, wm, wn, K1_APAD, aoff, boff);
  const unsigned As32 = (unsigned)__cvta_generic_to_shared(As);
  const unsigned Bs32 = As32 + (unsigned)K3A_AS * 2u;

  float d[2][6][4] = {};
  #pragma unroll
  for (int ks = 0; ks < 6; ++ks) {
    unsigned a[2][4], bf[3][4];
    ldsm_x4(a[0], As32 + aoff[0] + ks * 32);
    ldsm_x4(a[1], As32 + aoff[1] + ks * 32);
    ldsm_x4(bf[0], Bs32 + boff[0] + ks * 32);
    ldsm_x4(bf[1], Bs32 + boff[1] + ks * 32);
    ldsm_x4(bf[2], Bs32 + boff[2] + ks * 32);
    #pragma unroll
    for (int mi = 0; mi < 2; ++mi)
      #pragma unroll
      for (int p = 0; p < 3; ++p) {
        mma_f16(d[mi][2 * p],     a[mi], &bf[p][0]);
        mma_f16(d[mi][2 * p + 1], a[mi], &bf[p][2]);
      }
  }

  #pragma unroll
  for (int mi = 0; mi < 2; ++mi) {
    int r0 = n0 + wm * 32 + mi * 16 + (lane >> 2);
    #pragma unroll
    for (int ni = 0; ni < 6; ++ni) {
      int j = j0 + wn * 48 + ni * 8 + (lane & 3) * 2;
      float g0 = __ldg(&bng[j]),     b0 = __ldg(&bnb[j]);
      float g1 = __ldg(&bng[j + 1]), b1 = __ldg(&bnb[j + 1]);
      if (r0 < NPTS) {
        float v0 = fmaxf(fmaf(d[mi][ni][0], g0, b0), 0.f);
        float v1 = fmaxf(fmaf(d[mi][ni][1], g1, b1), 0.f);
        *(__half2*)&g_v2h[(size_t)r0 * DIMC + j] = __floats2half2_rn(v0, v1);
      }
      if (r0 + 8 < NPTS) {
        float v0 = fmaxf(fmaf(d[mi][ni][2], g0, b0), 0.f);
        float v1 = fmaxf(fmaf(d[mi][ni][3], g1, b1), 0.f);
        *(__half2*)&g_v2h[(size_t)(r0 + 8) * DIMC + j] = __floats2half2_rn(v0, v1);
      }
    }
  }
}

// =============================================================================
// K4: aggh = fp16(sum_d choice * sum_k cb*gather(v2h)); cb staged as fp16
// =============================================================================
#define K4_SMEM (15552 * 2)       // 31104 bytes

__global__ __launch_bounds__(256) void k4_agg(
    const int* __restrict__ neis, const float* __restrict__ cb)
{
  extern __shared__ char smem8[];
  __half2* ks = (__half2*)smem8;   // 7776 half2
  for (int i = threadIdx.x; i < 7776; i += 256) {
    float2 f = ((const float2*)cb)[i];
    ks[i] = __floats2half2_rn(f.x, f.y);
  }
  __syncthreads();

  const int lane = threadIdx.x & 31;
  const int w    = threadIdx.x >> 5;
  const int n0   = blockIdx.x * 128 + w * 16;

  for (int pi = 0; pi < 16; ++pi) {
    int n = n0 + pi;
    if (n >= NPTS) break;
    float agg[6] = {0.f,0.f,0.f,0.f,0.f,0.f};
    #pragma unroll
    for (int d = 0; d < 3; ++d) {
      const int* nd = neis + d*KTAP*NPTS + n;
      int rr[KTAP];
      #pragma unroll
      for (int k = 0; k < KTAP; ++k) rr[k] = __ldg(&nd[k*NPTS]);
      float pd[6] = {0.f,0.f,0.f,0.f,0.f,0.f};
      #pragma unroll 9
      for (int k = 0; k < KTAP; ++k) {
        int r = rr[k];
        if (r < NPTS) {
          const __half2* vr = (const __half2*)(g_v2h + (size_t)r * DIMC);
          const __half2* kk = ks + (d*KTAP + k)*96;
          #pragma unroll
          for (int i = 0; i < 3; ++i) {
            float2 f = __half22float2(vr[lane + 32*i]);
            float2 kf = __half22float2(kk[lane + 32*i]);
            pd[2*i]   = fmaf(kf.x, f.x, pd[2*i]);
            pd[2*i+1] = fmaf(kf.y, f.y, pd[2*i+1]);
          }
        }
      }
      #pragma unroll
      for (int i = 0; i < 3; ++i) {
        int c = lane*2 + 64*i;
        float ch = g_choice[n*24 + d*8 + (c/24)];
        agg[2*i]   += pd[2*i]   * ch;
        agg[2*i+1] += pd[2*i+1] * ch;
      }
    }
    #pragma unroll
    for (int i = 0; i < 3; ++i) {
      int c = lane*2 + 64*i;
      *(__half2*)&g_aggh[(size_t)n*DIMC + c] =
          __floats2half2_rn(agg[2*i], agg[2*i+1]);
    }
  }
}

// =============================================================================
// K5 (fp16 mma + ldmatrix): out = relu(BN( aggh @ out_w )) + x
// =============================================================================
#define K5_APAD 200
#define K5_SMEM ((128 + 96) * K5_APAD * 2)

__global__ __launch_bounds__(256) void k5_mma(
    const float* __restrict__ x, const float* __restrict__ bng,
    const float* __restrict__ bnb, float* __restrict__ out)
{
  extern __shared__ char smem8[];
  __half* As = (__half*)smem8;
  __half* Bs = As + 128 * K5_APAD;
  const int tid  = threadIdx.x;
  const int lane = tid & 31;
  const int wid  = tid >> 5;
  const int wm   = wid & 3;
  const int wn   = wid >> 2;
  const int n0   = blockIdx.x * 128;

  #pragma unroll
  for (int j = 0; j < 12; ++j) {
    int idx = tid + j * 256;
    int row = idx / 24, q = idx % 24;
    int n = n0 + row;
    cpa16z(As + row * K5_APAD + q * 8,
           g_aggh + (size_t)(n < NPTS ? n : 0) * DIMC + q * 8,
           (n < NPTS) ? 16 : 0);
  }
  #pragma unroll
  for (int j = 0; j < 9; ++j) {
    int idx = tid + j * 256;
    int row = idx / 24, q = idx % 24;
    cpa16(Bs + row * K5_APAD + q * 8, g_owh + row * DIMC + q * 8);
  }
  CPA_COMMIT(); CPA_WAIT0();
  __syncthreads();

  unsigned aoff[2], boff[3];
  frag_offsets(lane, wm, wn, K5_APAD, aoff, boff);
  const unsigned As32 = (unsigned)__cvta_generic_to_shared(As);
  const unsigned Bs32 = As32 + (unsigned)(128 * K5_APAD) * 2u;

  float d[2][6][4] = {};
  #pragma unroll
  for (int ks = 0; ks < 12; ++ks) {
    unsigned a[2][4], bf[3][4];
    ldsm_x4(a[0], As32 + aoff[0] + ks * 32);
    ldsm_x4(a[1], As32 + aoff[1] + ks * 32);
    ldsm_x4(bf[0], Bs32 + boff[0] + ks * 32);
    ldsm_x4(bf[1], Bs32 + boff[1] + ks * 32);
    ldsm_x4(bf[2], Bs32 + boff[2] + ks * 32);
    #pragma unroll
    for (int mi = 0; mi < 2; ++mi)
      #pragma unroll
      for (int p = 0; p < 3; ++p) {
        mma_f16(d[mi][2 * p],     a[mi], &bf[p][0]);
        mma_f16(d[mi][2 * p + 1], a[mi], &bf[p][2]);
      }
  }

  #pragma unroll
  for (int mi = 0; mi < 2; ++mi) {
    int r0 = n0 + wm * 32 + mi * 16 + (lane >> 2);
    #pragma unroll
    for (int ni = 0; ni < 6; ++ni) {
      int c = wn * 48 + ni * 8 + (lane & 3) * 2;
      float g0 = __ldg(&bng[c]),     b0 = __ldg(&bnb[c]);
      float g1 = __ldg(&bng[c + 1]), b1 = __ldg(&bnb[c + 1]);
      if (r0 < NPTS) {
        float2 v;
        v.x = fmaxf(fmaf(d[mi][ni][0], g0, b0), 0.f) + x[(size_t)r0 * PCH + c];
        v.y = fmaxf(fmaf(d[mi][ni][1], g1, b1), 0.f) + x[(size_t)r0 * PCH + c + 1];
        *(float2*)&out[(size_t)r0 * PCH + c] = v;
      }
      if (r0 + 8 < NPTS) {
        float2 v;
        v.x = fmaxf(fmaf(d[mi][ni][2], g0, b0), 0.f) + x[(size_t)(r0+8) * PCH + c];
        v.y = fmaxf(fmaf(d[mi][ni][3], g1, b1), 0.f) + x[(size_t)(r0+8) * PCH + c + 1];
        *(float2*)&out[(size_t)(r0 + 8) * PCH + c] = v;
      }
    }
  }
}

// =============================================================================
extern "C" void kernel_launch(void* const* d_in, const int* in_sizes, int n_in,
                              void* d_out, int out_size)
{
  const float* x    = (const float*)d_in[0];
  const int*   neis = (const int*)  d_in[1];
  const float* w_v1 = (const float*)d_in[2];
  const float* bn1g = (const float*)d_in[3];
  const float* bn1b = (const float*)d_in[4];
  const float* w_v2 = (const float*)d_in[5];
  const float* bn2g = (const float*)d_in[6];
  const float* bn2b = (const float*)d_in[7];
  const float* q_w  = (const float*)d_in[8];
  const float* cbk  = (const float*)d_in[9];
  const float* outw = (const float*)d_in[10];
  const float* obng = (const float*)d_in[11];
  const float* obnb = (const float*)d_in[12];
  float* out = (float*)d_out;

  // side stream + events, created once (first call is the non-captured
  // correctness run; creation never happens during capture)
  static cudaStream_t s2 = nullptr;
  static cudaEvent_t ev_fork = nullptr, ev_join = nullptr;
  if (!s2) {
    cudaStreamCreateWithFlags(&s2, cudaStreamNonBlocking);
    cudaEventCreateWithFlags(&ev_fork, cudaEventDisableTiming);
    cudaEventCreateWithFlags(&ev_join, cudaEventDisableTiming);
  }

  cudaFuncSetAttribute(k3a_z,   cudaFuncAttributeMaxDynamicSharedMemorySize, K3A_SMEM);
  cudaFuncSetAttribute(k1_mma,  cudaFuncAttributeMaxDynamicSharedMemorySize, K1_SMEM);
  cudaFuncSetAttribute(k2_mma,  cudaFuncAttributeMaxDynamicSharedMemorySize, K2_SMEM);
  cudaFuncSetAttribute(k4_agg,  cudaFuncAttributeMaxDynamicSharedMemorySize, K4_SMEM);
  cudaFuncSetAttribute(k5_mma,  cudaFuncAttributeMaxDynamicSharedMemorySize, K5_SMEM);

  // ---- chain A (main stream): cvt_x, cvt_w1 -> k1 -> cvt_w2 -> k2
  // ---- chain B (s2):          cvt_qw2 -> k3a -> k3b   (forked after cvt_x)
  k0_cvt_x   <<<512, 256>>>(x);                                  // 0
  k0_cvt_w1  <<<KTAP, 256>>>(w_v1);                              // 1
  cudaEventRecord(ev_fork, 0);
  cudaStreamWaitEvent(s2, ev_fork, 0);
  k0_cvt_qw2 <<<NTAP, 256, 0, s2>>>(q_w);                        // 2
  k1_mma     <<<(NPTS + 127) / 128, 256, K1_SMEM>>>(neis, bn1g, bn1b); // 3
  k3a_z      <<<dim3((NPTS + 127) / 128, 7), 256, K3A_SMEM, s2>>>();   // 4
  k3b_choice <<<(NPTS + 255) / 256, 256, 0, s2>>>(neis);         // 5
  cudaEventRecord(ev_join, s2);
  k0_cvt_w2  <<<(PCH * DIMC + 255) / 256, 256>>>(w_v2);          // 6
  k2_mma     <<<dim3((NPTS + 127) / 128, 2), 256, K2_SMEM>>>(bn2g, bn2b); // 7
  k0_cvt_ow  <<<(PCH * DIMC + 255) / 256, 256>>>(outw);          // 8
  cudaStreamWaitEvent(0, ev_join, 0);
  k4_agg     <<<(NPTS + 127) / 128, 256, K4_SMEM>>>(neis, cbk);  // 9
  k5_mma     <<<(NPTS + 127) / 128, 256, K5_SMEM>>>(x, obng, obnb, out); // 10
}